// round 14
// baseline (speedup 1.0000x reference)
#include <cuda_runtime.h>
#include <cuda_fp16.h>
#include <mma.h>
#include <cstdint>
using namespace nvcuda;

#define NB 2
#define L 6400
#define S 6400
#define C 256
#define GRID_W 80
#define BORDER 2

static constexpr float SIM_SCALE = 1.0f / 25.6f;   // 1/(C*TEMPERATURE)
static constexpr float THRESH = 0.2f;
static constexpr long long NLS = (long long)NB * L * S;

#define BM 128
#define BN 128
#define BK 32
#define NKT (C / BK)            // 8
#define STAGES 3
#define SSTR 48                 // smem half stride (96B rows)
#define STAGE_STRIDE 132        // floats
#define TILE_BYTES ((BM + BN) * SSTR * 2)      // 24576 per stage
#define SMEM_BYTES (STAGES * TILE_BYTES)       // 73728 >= stage overlay (67584)

// ---- small scratch only (large scratch must alias d_out: measured +225us
// penalty for big __device__ statics on this setup) ----
__device__ __align__(16) __half g_h0[NB * L * C];
__device__ __align__(16) __half g_h1[NB * S * C];
__device__ float g_rowsum[NB * L];
__device__ float g_colsum[NB * S];
__device__ float g_rowmax[NB * L];
__device__ int   g_rowarg[NB * L];
__device__ int   g_colmax[NB * S];   // float bits; conf > 0 so int order == float order

// ---------------------------------------------------------------------------
__device__ __forceinline__ uint32_t smem_u32(const void* p) {
    uint32_t a;
    asm("{ .reg .u64 t; cvta.to.shared.u64 t, %1; cvt.u32.u64 %0, t; }" : "=r"(a) : "l"(p));
    return a;
}
__device__ __forceinline__ void cp_async16(uint32_t saddr, const void* gaddr) {
    asm volatile("cp.async.cg.shared.global [%0], [%1], 16;" :: "r"(saddr), "l"(gaddr));
}
#define CP_COMMIT() asm volatile("cp.async.commit_group;" ::: "memory")
#define CP_WAIT(n)  asm volatile("cp.async.wait_group %0;" :: "n"(n) : "memory")

__device__ __forceinline__ void stcs_u2(void* p, uint2 v) {
    asm volatile("st.global.cs.v2.u32 [%0], {%1,%2};"
                 :: "l"(p), "r"(v.x), "r"(v.y) : "memory");
}

// ---------------------------------------------------------------------------
// 0) float -> half conversion + stats zeroing (fused; runs every replay)
// ---------------------------------------------------------------------------
#define CVT_CHUNKS (NB * L * C / 4)
__global__ __launch_bounds__(256) void cvt_k(const float4* __restrict__ x0,
                                             const float4* __restrict__ x1) {
    int i = blockIdx.x * blockDim.x + threadIdx.x;
    if (i < NB * S) { g_colsum[i] = 0.0f; g_colmax[i] = 0; g_rowsum[i] = 0.0f; }
    if (i < CVT_CHUNKS) {
        float4 v = x0[i];
        __half2* o = (__half2*)g_h0;
        o[2 * i]     = __floats2half2_rn(v.x, v.y);
        o[2 * i + 1] = __floats2half2_rn(v.z, v.w);
    } else if (i < 2 * CVT_CHUNKS) {
        int j = i - CVT_CHUNKS;
        float4 v = x1[j];
        __half2* o = (__half2*)g_h1;
        o[2 * j]     = __floats2half2_rn(v.x, v.y);
        o[2 * j + 1] = __floats2half2_rn(v.z, v.w);
    }
}

// ---------------------------------------------------------------------------
// 1) FP16 WMMA GEMM: 128x128 CTA tile, 4 warps x 64x64 warp tiles,
//    3-stage cp.async; fused epilogue: exp + E fp16 store with row sums
//    (warp shfl) and col sums (register accumulators) folded into the
//    single store pass — no separate smem reduction loops
// ---------------------------------------------------------------------------
__global__ __launch_bounds__(128, 3) void gemm_exp_k(__half* __restrict__ Eh) {
    extern __shared__ char smem[];
    const uint32_t sb = smem_u32(smem);
    float* stage = (float*)smem;        // overlays stage buffers after mainloop

    const int t = threadIdx.x;
    const int wid = t >> 5;
    const int lid = t & 31;
    const int wm = wid >> 1;       // 0..1 -> 64-row band
    const int wn = wid & 1;        // 0..1 -> 64-col band
    const int n = blockIdx.z;
    const int l0 = blockIdx.y * BM, s0 = blockIdx.x * BN;

    const __half* A = g_h0 + (size_t)n * L * C;
    const __half* B = g_h1 + (size_t)n * S * C;
    __half* Eo = Eh + (size_t)n * L * S;

    wmma::fragment<wmma::accumulator, 16, 16, 16, float> acc[4][4];
    #pragma unroll
    for (int i = 0; i < 4; i++)
        #pragma unroll
        for (int j = 0; j < 4; j++)
            wmma::fill_fragment(acc[i][j], 0.0f);

    // tile loader: A 128x32 + B 128x32 = 1024 16B-chunks, 8 per thread
    auto load_tile = [&](int kt) {
        const int k0 = kt * BK;
        const uint32_t st = (kt % STAGES) * TILE_BYTES;
        #pragma unroll
        for (int i = 0; i < 4; i++) {
            int c = t + i * 128;               // 0..511
            int r = c >> 2, u = c & 3;
            uint32_t so = st + (uint32_t)(r * SSTR + u * 8) * 2;
            cp_async16(sb + so, A + (size_t)(l0 + r) * C + k0 + u * 8);
            cp_async16(sb + so + BM * SSTR * 2, B + (size_t)(s0 + r) * C + k0 + u * 8);
        }
        CP_COMMIT();
    };

    load_tile(0);
    load_tile(1);

    for (int kt = 0; kt < NKT; kt++) {
        CP_WAIT(1);
        __syncthreads();
        if (kt + 2 < NKT) load_tile(kt + 2);
        else              CP_COMMIT();

        const __half* Ab = (const __half*)(smem + (kt % STAGES) * TILE_BYTES);
        const __half* Bb = Ab + BM * SSTR;
        #pragma unroll
        for (int ks = 0; ks < BK; ks += 16) {
            wmma::fragment<wmma::matrix_a, 16, 16, 16, __half, wmma::row_major> af[4];
            wmma::fragment<wmma::matrix_b, 16, 16, 16, __half, wmma::col_major> bf[4];
            #pragma unroll
            for (int i = 0; i < 4; i++)
                wmma::load_matrix_sync(af[i], Ab + (wm * 64 + i * 16) * SSTR + ks, SSTR);
            #pragma unroll
            for (int j = 0; j < 4; j++)
                wmma::load_matrix_sync(bf[j], Bb + (wn * 64 + j * 16) * SSTR + ks, SSTR);
            #pragma unroll
            for (int i = 0; i < 4; i++)
                #pragma unroll
                for (int j = 0; j < 4; j++)
                    wmma::mma_sync(acc[i][j], af[i], bf[j], acc[i][j]);
        }
    }
    __syncthreads();

    // exp on accumulators, stage to smem (fp32)
    #pragma unroll
    for (int i = 0; i < 4; i++) {
        #pragma unroll
        for (int j = 0; j < 4; j++) {
            #pragma unroll
            for (int e = 0; e < acc[i][j].num_elements; e++)
                acc[i][j].x[e] = __expf(acc[i][j].x[e] * SIM_SCALE);
            wmma::store_matrix_sync(
                &stage[(size_t)(wm * 64 + i * 16) * STAGE_STRIDE + wn * 64 + j * 16],
                acc[i][j], STAGE_STRIDE, wmma::mem_row_major);
        }
    }
    __syncthreads();

    // ---- single-pass epilogue over stage:
    // iteration it: idx = t + it*128 -> r = (t>>5)+it*4 (whole warp on row r),
    //                                   q = t&31      (fixed columns per thread)
    float cs0 = 0.0f, cs1 = 0.0f, cs2 = 0.0f, cs3 = 0.0f;   // cols q*4..q*4+3
    #pragma unroll
    for (int it = 0; it < 32; it++) {
        const int r = wid + it * 4;
        const int q = lid;
        float4 f = *(float4*)&stage[r * STAGE_STRIDE + q * 4];
        // col partial sums (register)
        cs0 += f.x; cs1 += f.y; cs2 += f.z; cs3 += f.w;
        // row sum: warp-level reduce of this row's 4-element chunks
        float rs = (f.x + f.y) + (f.z + f.w);
        #pragma unroll
        for (int o = 16; o; o >>= 1) rs += __shfl_xor_sync(0xFFFFFFFFu, rs, o);
        if (lid == 0) atomicAdd(&g_rowsum[n * L + l0 + r], rs);
        // streaming fp16 E store
        __half2 h0 = __floats2half2_rn(f.x, f.y);
        __half2 h1 = __floats2half2_rn(f.z, f.w);
        uint2 u;
        u.x = *(uint32_t*)&h0;
        u.y = *(uint32_t*)&h1;
        stcs_u2(&Eo[(size_t)(l0 + r) * S + s0 + q * 4], u);
    }
    __syncthreads();   // all stage reads done; reuse for col cross-group reduce

    // col partials: group g = wid holds cols lid*4..lid*4+3; reduce across 4 groups
    float* sm_col = stage;                      // [4][128]
    sm_col[wid * 128 + lid * 4 + 0] = cs0;
    sm_col[wid * 128 + lid * 4 + 1] = cs1;
    sm_col[wid * 128 + lid * 4 + 2] = cs2;
    sm_col[wid * 128 + lid * 4 + 3] = cs3;
    __syncthreads();
    {
        float s = sm_col[t] + sm_col[128 + t] + sm_col[256 + t] + sm_col[384 + t];
        atomicAdd(&g_colsum[n * S + s0 + t], s);
    }
}

// ---------------------------------------------------------------------------
// 2) conf = E^2/(rowsum*colsum); rowmax+argmax, colmax (32-row stripes)
// ---------------------------------------------------------------------------
#define CROWS 32
__global__ __launch_bounds__(256) void conf_k(const __half* __restrict__ Eh,
                                              float* __restrict__ conf) {
    const int n = blockIdx.y;
    const int l0 = blockIdx.x * CROWS;
    const int t = threadIdx.x;
    __shared__ float s_val[8];
    __shared__ int   s_arg[8];

    float ic[25], cm[25];
    #pragma unroll
    for (int k = 0; k < 25; k++) {
        ic[k] = 1.0f / g_colsum[n * S + t + k * 256];
        cm[k] = 0.0f;
    }

    for (int r = 0; r < CROWS; r++) {
        const int l = l0 + r;
        const size_t off = ((size_t)n * L + l) * S;
        const float ir = 1.0f / g_rowsum[n * L + l];
        float rmax = 0.0f; int rarg = t;
        #pragma unroll
        for (int k = 0; k < 25; k++) {
            int s = t + k * 256;
            float e = __half2float(Eh[off + s]);
            float c = e * e * ir * ic[k];
            conf[off + s] = c;
            cm[k] = fmaxf(cm[k], c);
            if (c > rmax) { rmax = c; rarg = s; }
        }
        #pragma unroll
        for (int o = 16; o; o >>= 1) {
            float ov = __shfl_xor_sync(0xFFFFFFFFu, rmax, o);
            int   oa = __shfl_xor_sync(0xFFFFFFFFu, rarg, o);
            if (ov > rmax) { rmax = ov; rarg = oa; }
        }
        if ((t & 31) == 0) { s_val[t >> 5] = rmax; s_arg[t >> 5] = rarg; }
        __syncthreads();
        if (t == 0) {
            #pragma unroll
            for (int w = 1; w < 8; w++)
                if (s_val[w] > rmax) { rmax = s_val[w]; rarg = s_arg[w]; }
            g_rowmax[n * L + l] = rmax;
            g_rowarg[n * L + l] = rarg;
        }
        __syncthreads();
    }
    #pragma unroll
    for (int k = 0; k < 25; k++)
        atomicMax(&g_colmax[n * S + t + k * 256], __float_as_int(cm[k]));
}

// ---------------------------------------------------------------------------
// 3) dense final: writes full mask + scores rows (proven R11 config)
// ---------------------------------------------------------------------------
__device__ __forceinline__ bool border_ok(int i) {
    int h = i / GRID_W, w = i % GRID_W;
    return (h >= BORDER) && (h < GRID_W - BORDER) && (w >= BORDER) && (w < GRID_W - BORDER);
}
__global__ __launch_bounds__(256) void final_dense_k(float* __restrict__ maskp,
                                                     float* __restrict__ scoresp) {
    const int n = blockIdx.y, l = blockIdx.x;
    const int t = threadIdx.x;
    const size_t off = ((size_t)n * L + l) * S;
    const float rmax = g_rowmax[n * L + l];
    const int rarg = g_rowarg[n * L + l];
    const bool rcond = (rmax > THRESH) && border_ok(l) &&
                       (__float_as_int(rmax) == g_colmax[n * S + rarg]) &&
                       border_ok(rarg);
    #pragma unroll
    for (int k = 0; k < 25; k++) {
        int s = t + k * 256;
        bool m = rcond && (s == rarg);
        maskp[off + s]   = m ? 1.0f : 0.0f;
        scoresp[off + s] = m ? rmax : 0.0f;
    }
}

// ---------------------------------------------------------------------------
extern "C" void kernel_launch(void* const* d_in, const int* in_sizes, int n_in,
                              void* d_out, int out_size) {
    const float* x0 = (const float*)d_in[0];
    const float* x1 = (const float*)d_in[1];

    float* conf    = (float*)d_out;          // [NB, L, S]
    float* maskp   = conf + NLS;             // [NB, L, S]
    float* scoresp = conf + 2 * NLS;         // [NB, L, S]
    __half* Eh     = (__half*)scoresp;       // fp16 E scratch in scores region
                                             // (consumed by conf_k before
                                             //  final_dense_k overwrites)

    cudaFuncSetAttribute(gemm_exp_k, cudaFuncAttributeMaxDynamicSharedMemorySize, SMEM_BYTES);

    cvt_k<<<(2 * CVT_CHUNKS + 255) / 256, 256>>>((const float4*)x0, (const float4*)x1);
    gemm_exp_k<<<dim3(S / BN, L / BM, NB), 128, SMEM_BYTES>>>(Eh);
    conf_k<<<dim3(L / CROWS, NB), 256>>>(Eh, conf);
    final_dense_k<<<dim3(L, NB), 256>>>(maskp, scoresp);
}

// round 15
// speedup vs baseline: 1.0922x; 1.0922x over previous
#include <cuda_runtime.h>
#include <cuda_fp16.h>
#include <mma.h>
#include <cstdint>
using namespace nvcuda;

#define NB 2
#define L 6400
#define S 6400
#define C 256
#define GRID_W 80
#define BORDER 2

static constexpr float SIM_SCALE = 1.0f / 25.6f;   // 1/(C*TEMPERATURE)
static constexpr float THRESH = 0.2f;
static constexpr long long NLS = (long long)NB * L * S;

#define BM 128
#define BN 128
#define BK 32
#define NKT (C / BK)            // 8
#define STAGES 3
#define SSTR 48                 // smem half stride (96B rows)
#define STAGE_STRIDE 132        // floats
#define TILE_BYTES ((BM + BN) * SSTR * 2)      // 24576 per stage
#define SMEM_BYTES (STAGES * TILE_BYTES)       // 73728 >= stage overlay (67584)

// ---- small scratch only (large scratch must alias d_out: measured +225us
// penalty for big __device__ statics on this setup) ----
__device__ __align__(16) __half g_h0[NB * L * C];
__device__ __align__(16) __half g_h1[NB * S * C];
__device__ float g_rowsum[NB * L];
__device__ float g_colsum[NB * S];
__device__ float g_rowmax[NB * L];
__device__ int   g_rowarg[NB * L];
__device__ int   g_colmax[NB * S];   // float bits; conf > 0 so int order == float order

// ---------------------------------------------------------------------------
__device__ __forceinline__ uint32_t smem_u32(const void* p) {
    uint32_t a;
    asm("{ .reg .u64 t; cvta.to.shared.u64 t, %1; cvt.u32.u64 %0, t; }" : "=r"(a) : "l"(p));
    return a;
}
__device__ __forceinline__ void cp_async16(uint32_t saddr, const void* gaddr) {
    asm volatile("cp.async.cg.shared.global [%0], [%1], 16;" :: "r"(saddr), "l"(gaddr));
}
#define CP_COMMIT() asm volatile("cp.async.commit_group;" ::: "memory")
#define CP_WAIT(n)  asm volatile("cp.async.wait_group %0;" :: "n"(n) : "memory")

// ---------------------------------------------------------------------------
// 0) float -> half conversion + stats zeroing (fused; runs every replay)
// ---------------------------------------------------------------------------
#define CVT_CHUNKS (NB * L * C / 4)
__global__ __launch_bounds__(256) void cvt_k(const float4* __restrict__ x0,
                                             const float4* __restrict__ x1) {
    int i = blockIdx.x * blockDim.x + threadIdx.x;
    if (i < NB * S) { g_colsum[i] = 0.0f; g_colmax[i] = 0; g_rowsum[i] = 0.0f; }
    if (i < CVT_CHUNKS) {
        float4 v = x0[i];
        __half2* o = (__half2*)g_h0;
        o[2 * i]     = __floats2half2_rn(v.x, v.y);
        o[2 * i + 1] = __floats2half2_rn(v.z, v.w);
    } else if (i < 2 * CVT_CHUNKS) {
        int j = i - CVT_CHUNKS;
        float4 v = x1[j];
        __half2* o = (__half2*)g_h1;
        o[2 * j]     = __floats2half2_rn(v.x, v.y);
        o[2 * j + 1] = __floats2half2_rn(v.z, v.w);
    }
}

// ---------------------------------------------------------------------------
// 1) FP16 WMMA GEMM: 128x128 CTA tile, 4 warps x 64x64 warp tiles,
//    3-stage cp.async, 3 CTAs/SM; epilogue: exp -> smem stage ->
//    row sums (vectorized LDS loop) + col sums folded into the E-store loop
// ---------------------------------------------------------------------------
__global__ __launch_bounds__(128, 3) void gemm_exp_k(__half* __restrict__ Eh) {
    extern __shared__ char smem[];
    const uint32_t sb = smem_u32(smem);
    float* stage = (float*)smem;        // overlays stage buffers after mainloop

    const int t = threadIdx.x;
    const int wid = t >> 5;
    const int lid = t & 31;
    const int wm = wid >> 1;       // 0..1 -> 64-row band
    const int wn = wid & 1;        // 0..1 -> 64-col band
    const int n = blockIdx.z;
    const int l0 = blockIdx.y * BM, s0 = blockIdx.x * BN;

    const __half* A = g_h0 + (size_t)n * L * C;
    const __half* B = g_h1 + (size_t)n * S * C;
    __half* Eo = Eh + (size_t)n * L * S;

    wmma::fragment<wmma::accumulator, 16, 16, 16, float> acc[4][4];
    #pragma unroll
    for (int i = 0; i < 4; i++)
        #pragma unroll
        for (int j = 0; j < 4; j++)
            wmma::fill_fragment(acc[i][j], 0.0f);

    // tile loader: A 128x32 + B 128x32 = 1024 16B-chunks, 8 per thread
    auto load_tile = [&](int kt) {
        const int k0 = kt * BK;
        const uint32_t st = (kt % STAGES) * TILE_BYTES;
        #pragma unroll
        for (int i = 0; i < 4; i++) {
            int c = t + i * 128;               // 0..511
            int r = c >> 2, u = c & 3;
            uint32_t so = st + (uint32_t)(r * SSTR + u * 8) * 2;
            cp_async16(sb + so, A + (size_t)(l0 + r) * C + k0 + u * 8);
            cp_async16(sb + so + BM * SSTR * 2, B + (size_t)(s0 + r) * C + k0 + u * 8);
        }
        CP_COMMIT();
    };

    load_tile(0);
    load_tile(1);

    for (int kt = 0; kt < NKT; kt++) {
        CP_WAIT(1);
        __syncthreads();
        if (kt + 2 < NKT) load_tile(kt + 2);
        else              CP_COMMIT();

        const __half* Ab = (const __half*)(smem + (kt % STAGES) * TILE_BYTES);
        const __half* Bb = Ab + BM * SSTR;
        #pragma unroll
        for (int ks = 0; ks < BK; ks += 16) {
            wmma::fragment<wmma::matrix_a, 16, 16, 16, __half, wmma::row_major> af[4];
            wmma::fragment<wmma::matrix_b, 16, 16, 16, __half, wmma::col_major> bf[4];
            #pragma unroll
            for (int i = 0; i < 4; i++)
                wmma::load_matrix_sync(af[i], Ab + (wm * 64 + i * 16) * SSTR + ks, SSTR);
            #pragma unroll
            for (int j = 0; j < 4; j++)
                wmma::load_matrix_sync(bf[j], Bb + (wn * 64 + j * 16) * SSTR + ks, SSTR);
            #pragma unroll
            for (int i = 0; i < 4; i++)
                #pragma unroll
                for (int j = 0; j < 4; j++)
                    wmma::mma_sync(acc[i][j], af[i], bf[j], acc[i][j]);
        }
    }
    __syncthreads();

    // exp on accumulators, stage to smem (fp32)
    #pragma unroll
    for (int i = 0; i < 4; i++) {
        #pragma unroll
        for (int j = 0; j < 4; j++) {
            #pragma unroll
            for (int e = 0; e < acc[i][j].num_elements; e++)
                acc[i][j].x[e] = __expf(acc[i][j].x[e] * SIM_SCALE);
            wmma::store_matrix_sync(
                &stage[(size_t)(wm * 64 + i * 16) * STAGE_STRIDE + wn * 64 + j * 16],
                acc[i][j], STAGE_STRIDE, wmma::mem_row_major);
        }
    }
    __syncthreads();

    {   // row partial sums: thread t -> full row t (32 float4, conflict-free)
        float s = 0.0f;
        const float4* row4 = (const float4*)&stage[t * STAGE_STRIDE];
        #pragma unroll 8
        for (int c = 0; c < 32; c++) {
            float4 f = row4[c];
            s += (f.x + f.y) + (f.z + f.w);
        }
        atomicAdd(&g_rowsum[n * L + l0 + t], s);
    }

    // E-store loop with col sums folded in: iteration it covers
    // r = wid + it*4 (whole warp on one row), q = lid (fixed cols per thread)
    float cs0 = 0.0f, cs1 = 0.0f, cs2 = 0.0f, cs3 = 0.0f;   // cols lid*4..lid*4+3
    #pragma unroll
    for (int it = 0; it < 32; it++) {
        const int r = wid + it * 4;
        float4 f = *(float4*)&stage[r * STAGE_STRIDE + lid * 4];
        cs0 += f.x; cs1 += f.y; cs2 += f.z; cs3 += f.w;
        __half2 h0 = __floats2half2_rn(f.x, f.y);
        __half2 h1 = __floats2half2_rn(f.z, f.w);
        uint2 u;
        u.x = *(uint32_t*)&h0;
        u.y = *(uint32_t*)&h1;
        *(uint2*)&Eo[(size_t)(l0 + r) * S + s0 + lid * 4] = u;
    }
    __syncthreads();   // all stage reads done; reuse it for the col exchange

    // col partials: group wid holds cols lid*4..lid*4+3; reduce the 4 groups
    float* sm_col = stage;                      // [4][128] floats
    sm_col[wid * 128 + lid * 4 + 0] = cs0;
    sm_col[wid * 128 + lid * 4 + 1] = cs1;
    sm_col[wid * 128 + lid * 4 + 2] = cs2;
    sm_col[wid * 128 + lid * 4 + 3] = cs3;
    __syncthreads();
    {
        float s = sm_col[t] + sm_col[128 + t] + sm_col[256 + t] + sm_col[384 + t];
        atomicAdd(&g_colsum[n * S + s0 + t], s);
    }
}

// ---------------------------------------------------------------------------
// 2) conf = E^2/(rowsum*colsum); rowmax+argmax, colmax (32-row stripes)
// ---------------------------------------------------------------------------
#define CROWS 32
__global__ __launch_bounds__(256) void conf_k(const __half* __restrict__ Eh,
                                              float* __restrict__ conf) {
    const int n = blockIdx.y;
    const int l0 = blockIdx.x * CROWS;
    const int t = threadIdx.x;
    __shared__ float s_val[8];
    __shared__ int   s_arg[8];

    float ic[25], cm[25];
    #pragma unroll
    for (int k = 0; k < 25; k++) {
        ic[k] = 1.0f / g_colsum[n * S + t + k * 256];
        cm[k] = 0.0f;
    }

    for (int r = 0; r < CROWS; r++) {
        const int l = l0 + r;
        const size_t off = ((size_t)n * L + l) * S;
        const float ir = 1.0f / g_rowsum[n * L + l];
        float rmax = 0.0f; int rarg = t;
        #pragma unroll
        for (int k = 0; k < 25; k++) {
            int s = t + k * 256;
            float e = __half2float(Eh[off + s]);
            float c = e * e * ir * ic[k];
            conf[off + s] = c;
            cm[k] = fmaxf(cm[k], c);
            if (c > rmax) { rmax = c; rarg = s; }
        }
        #pragma unroll
        for (int o = 16; o; o >>= 1) {
            float ov = __shfl_xor_sync(0xFFFFFFFFu, rmax, o);
            int   oa = __shfl_xor_sync(0xFFFFFFFFu, rarg, o);
            if (ov > rmax) { rmax = ov; rarg = oa; }
        }
        if ((t & 31) == 0) { s_val[t >> 5] = rmax; s_arg[t >> 5] = rarg; }
        __syncthreads();
        if (t == 0) {
            #pragma unroll
            for (int w = 1; w < 8; w++)
                if (s_val[w] > rmax) { rmax = s_val[w]; rarg = s_arg[w]; }
            g_rowmax[n * L + l] = rmax;
            g_rowarg[n * L + l] = rarg;
        }
        __syncthreads();
    }
    #pragma unroll
    for (int k = 0; k < 25; k++)
        atomicMax(&g_colmax[n * S + t + k * 256], __float_as_int(cm[k]));
}

// ---------------------------------------------------------------------------
// 3) dense final: writes full mask + scores rows (proven R11 config)
// ---------------------------------------------------------------------------
__device__ __forceinline__ bool border_ok(int i) {
    int h = i / GRID_W, w = i % GRID_W;
    return (h >= BORDER) && (h < GRID_W - BORDER) && (w >= BORDER) && (w < GRID_W - BORDER);
}
__global__ __launch_bounds__(256) void final_dense_k(float* __restrict__ maskp,
                                                     float* __restrict__ scoresp) {
    const int n = blockIdx.y, l = blockIdx.x;
    const int t = threadIdx.x;
    const size_t off = ((size_t)n * L + l) * S;
    const float rmax = g_rowmax[n * L + l];
    const int rarg = g_rowarg[n * L + l];
    const bool rcond = (rmax > THRESH) && border_ok(l) &&
                       (__float_as_int(rmax) == g_colmax[n * S + rarg]) &&
                       border_ok(rarg);
    #pragma unroll
    for (int k = 0; k < 25; k++) {
        int s = t + k * 256;
        bool m = rcond && (s == rarg);
        maskp[off + s]   = m ? 1.0f : 0.0f;
        scoresp[off + s] = m ? rmax : 0.0f;
    }
}

// ---------------------------------------------------------------------------
extern "C" void kernel_launch(void* const* d_in, const int* in_sizes, int n_in,
                              void* d_out, int out_size) {
    const float* x0 = (const float*)d_in[0];
    const float* x1 = (const float*)d_in[1];

    float* conf    = (float*)d_out;          // [NB, L, S]
    float* maskp   = conf + NLS;             // [NB, L, S]
    float* scoresp = conf + 2 * NLS;         // [NB, L, S]
    __half* Eh     = (__half*)scoresp;       // fp16 E scratch in scores region
                                             // (consumed by conf_k before
                                             //  final_dense_k overwrites)

    cudaFuncSetAttribute(gemm_exp_k, cudaFuncAttributeMaxDynamicSharedMemorySize, SMEM_BYTES);

    cvt_k<<<(2 * CVT_CHUNKS + 255) / 256, 256>>>((const float4*)x0, (const float4*)x1);
    gemm_exp_k<<<dim3(S / BN, L / BM, NB), 128, SMEM_BYTES>>>(Eh);
    conf_k<<<dim3(L / CROWS, NB), 256>>>(Eh, conf);
    final_dense_k<<<dim3(L, NB), 256>>>(maskp, scoresp);
}

// round 16
// speedup vs baseline: 1.0975x; 1.0048x over previous
#include <cuda_runtime.h>
#include <cuda_fp16.h>
#include <mma.h>
#include <cstdint>
using namespace nvcuda;

#define NB 2
#define L 6400
#define S 6400
#define C 256
#define GRID_W 80
#define BORDER 2

static constexpr float SIM_SCALE = 1.0f / 25.6f;   // 1/(C*TEMPERATURE)
static constexpr float THRESH = 0.2f;
static constexpr long long NLS = (long long)NB * L * S;

#define BM 128
#define BN 128
#define BK 32
#define NKT (C / BK)            // 8
#define STAGES 3
#define SSTR 40                 // smem half stride (80B rows: conflict-free LDSM)
#define STAGE_STRIDE 132        // floats
#define TILE_BYTES ((BM + BN) * SSTR * 2)      // 20480 per stage
#define STAGE_BYTES (BM * STAGE_STRIDE * 4)    // 67584
#define SMEM_BYTES  (STAGE_BYTES)              // > 3*TILE_BYTES (61440)

// ---- small scratch only (large scratch must alias d_out: measured +225us
// penalty for big __device__ statics on this setup) ----
__device__ __align__(16) __half g_h0[NB * L * C];
__device__ __align__(16) __half g_h1[NB * S * C];
__device__ float g_rowsum[NB * L];
__device__ float g_colsum[NB * S];
__device__ float g_rowmax[NB * L];
__device__ int   g_rowarg[NB * L];
__device__ int   g_colmax[NB * S];   // float bits; conf > 0 so int order == float order

// ---------------------------------------------------------------------------
__device__ __forceinline__ uint32_t smem_u32(const void* p) {
    uint32_t a;
    asm("{ .reg .u64 t; cvta.to.shared.u64 t, %1; cvt.u32.u64 %0, t; }" : "=r"(a) : "l"(p));
    return a;
}
__device__ __forceinline__ void cp_async16(uint32_t saddr, const void* gaddr) {
    asm volatile("cp.async.cg.shared.global [%0], [%1], 16;" :: "r"(saddr), "l"(gaddr));
}
#define CP_COMMIT() asm volatile("cp.async.commit_group;" ::: "memory")
#define CP_WAIT(n)  asm volatile("cp.async.wait_group %0;" :: "n"(n) : "memory")

// ---------------------------------------------------------------------------
// 0) float -> half conversion + stats zeroing (fused; runs every replay)
// ---------------------------------------------------------------------------
#define CVT_CHUNKS (NB * L * C / 4)
__global__ __launch_bounds__(256) void cvt_k(const float4* __restrict__ x0,
                                             const float4* __restrict__ x1) {
    int i = blockIdx.x * blockDim.x + threadIdx.x;
    if (i < NB * S) { g_colsum[i] = 0.0f; g_colmax[i] = 0; g_rowsum[i] = 0.0f; }
    if (i < CVT_CHUNKS) {
        float4 v = x0[i];
        __half2* o = (__half2*)g_h0;
        o[2 * i]     = __floats2half2_rn(v.x, v.y);
        o[2 * i + 1] = __floats2half2_rn(v.z, v.w);
    } else if (i < 2 * CVT_CHUNKS) {
        int j = i - CVT_CHUNKS;
        float4 v = x1[j];
        __half2* o = (__half2*)g_h1;
        o[2 * j]     = __floats2half2_rn(v.x, v.y);
        o[2 * j + 1] = __floats2half2_rn(v.z, v.w);
    }
}

// ---------------------------------------------------------------------------
// 1) FP16 WMMA GEMM: 128x128 CTA tile, 4 warps x 64x64 warp tiles,
//    3-stage cp.async, 3 CTAs/SM, conflict-free 80B smem rows; epilogue:
//    exp -> smem stage -> row sums (LDS loop) + col sums folded in E-store
// ---------------------------------------------------------------------------
__global__ __launch_bounds__(128, 3) void gemm_exp_k(__half* __restrict__ Eh) {
    extern __shared__ char smem[];
    const uint32_t sb = smem_u32(smem);
    float* stage = (float*)smem;        // overlays stage buffers after mainloop

    const int t = threadIdx.x;
    const int wid = t >> 5;
    const int lid = t & 31;
    const int wm = wid >> 1;       // 0..1 -> 64-row band
    const int wn = wid & 1;        // 0..1 -> 64-col band
    const int n = blockIdx.z;
    const int l0 = blockIdx.y * BM, s0 = blockIdx.x * BN;

    const __half* A = g_h0 + (size_t)n * L * C;
    const __half* B = g_h1 + (size_t)n * S * C;
    __half* Eo = Eh + (size_t)n * L * S;

    wmma::fragment<wmma::accumulator, 16, 16, 16, float> acc[4][4];
    #pragma unroll
    for (int i = 0; i < 4; i++)
        #pragma unroll
        for (int j = 0; j < 4; j++)
            wmma::fill_fragment(acc[i][j], 0.0f);

    // tile loader: A 128x32 + B 128x32 = 1024 16B-chunks, 8 per thread
    auto load_tile = [&](int kt) {
        const int k0 = kt * BK;
        const uint32_t st = (kt % STAGES) * TILE_BYTES;
        #pragma unroll
        for (int i = 0; i < 4; i++) {
            int c = t + i * 128;               // 0..511
            int r = c >> 2, u = c & 3;
            uint32_t so = st + (uint32_t)(r * SSTR + u * 8) * 2;
            cp_async16(sb + so, A + (size_t)(l0 + r) * C + k0 + u * 8);
            cp_async16(sb + so + BM * SSTR * 2, B + (size_t)(s0 + r) * C + k0 + u * 8);
        }
        CP_COMMIT();
    };

    load_tile(0);
    load_tile(1);

    for (int kt = 0; kt < NKT; kt++) {
        CP_WAIT(1);
        __syncthreads();
        if (kt + 2 < NKT) load_tile(kt + 2);
        else              CP_COMMIT();

        const __half* Ab = (const __half*)(smem + (kt % STAGES) * TILE_BYTES);
        const __half* Bb = Ab + BM * SSTR;
        #pragma unroll
        for (int ks = 0; ks < BK; ks += 16) {
            wmma::fragment<wmma::matrix_a, 16, 16, 16, __half, wmma::row_major> af[4];
            wmma::fragment<wmma::matrix_b, 16, 16, 16, __half, wmma::col_major> bf[4];
            #pragma unroll
            for (int i = 0; i < 4; i++)
                wmma::load_matrix_sync(af[i], Ab + (wm * 64 + i * 16) * SSTR + ks, SSTR);
            #pragma unroll
            for (int j = 0; j < 4; j++)
                wmma::load_matrix_sync(bf[j], Bb + (wn * 64 + j * 16) * SSTR + ks, SSTR);
            #pragma unroll
            for (int i = 0; i < 4; i++)
                #pragma unroll
                for (int j = 0; j < 4; j++)
                    wmma::mma_sync(acc[i][j], af[i], bf[j], acc[i][j]);
        }
    }
    __syncthreads();

    // exp on accumulators, stage to smem (fp32)
    #pragma unroll
    for (int i = 0; i < 4; i++) {
        #pragma unroll
        for (int j = 0; j < 4; j++) {
            #pragma unroll
            for (int e = 0; e < acc[i][j].num_elements; e++)
                acc[i][j].x[e] = __expf(acc[i][j].x[e] * SIM_SCALE);
            wmma::store_matrix_sync(
                &stage[(size_t)(wm * 64 + i * 16) * STAGE_STRIDE + wn * 64 + j * 16],
                acc[i][j], STAGE_STRIDE, wmma::mem_row_major);
        }
    }
    __syncthreads();

    {   // row partial sums: thread t -> full row t (32 float4, vectorized)
        float s = 0.0f;
        const float4* row4 = (const float4*)&stage[t * STAGE_STRIDE];
        #pragma unroll 8
        for (int c = 0; c < 32; c++) {
            float4 f = row4[c];
            s += (f.x + f.y) + (f.z + f.w);
        }
        atomicAdd(&g_rowsum[n * L + l0 + t], s);
    }

    // E-store loop with col sums folded in: iteration it covers
    // r = wid + it*4 (whole warp on one row), q = lid (fixed cols per thread)
    float cs0 = 0.0f, cs1 = 0.0f, cs2 = 0.0f, cs3 = 0.0f;   // cols lid*4..lid*4+3
    #pragma unroll
    for (int it = 0; it < 32; it++) {
        const int r = wid + it * 4;
        float4 f = *(float4*)&stage[r * STAGE_STRIDE + lid * 4];
        cs0 += f.x; cs1 += f.y; cs2 += f.z; cs3 += f.w;
        __half2 h0 = __floats2half2_rn(f.x, f.y);
        __half2 h1 = __floats2half2_rn(f.z, f.w);
        uint2 u;
        u.x = *(uint32_t*)&h0;
        u.y = *(uint32_t*)&h1;
        *(uint2*)&Eo[(size_t)(l0 + r) * S + s0 + lid * 4] = u;
    }
    __syncthreads();   // all stage reads done; reuse it for the col exchange

    // col partials: group wid holds cols lid*4..lid*4+3; reduce the 4 groups
    float* sm_col = stage;                      // [4][128] floats
    sm_col[wid * 128 + lid * 4 + 0] = cs0;
    sm_col[wid * 128 + lid * 4 + 1] = cs1;
    sm_col[wid * 128 + lid * 4 + 2] = cs2;
    sm_col[wid * 128 + lid * 4 + 3] = cs3;
    __syncthreads();
    {
        float s = sm_col[t] + sm_col[128 + t] + sm_col[256 + t] + sm_col[384 + t];
        atomicAdd(&g_colsum[n * S + s0 + t], s);
    }
}

// ---------------------------------------------------------------------------
// 2) conf = E^2/(rowsum*colsum); rowmax+argmax, colmax (32-row stripes)
// ---------------------------------------------------------------------------
#define CROWS 32
__global__ __launch_bounds__(256) void conf_k(const __half* __restrict__ Eh,
                                              float* __restrict__ conf) {
    const int n = blockIdx.y;
    const int l0 = blockIdx.x * CROWS;
    const int t = threadIdx.x;
    __shared__ float s_val[8];
    __shared__ int   s_arg[8];

    float ic[25], cm[25];
    #pragma unroll
    for (int k = 0; k < 25; k++) {
        ic[k] = 1.0f / g_colsum[n * S + t + k * 256];
        cm[k] = 0.0f;
    }

    for (int r = 0; r < CROWS; r++) {
        const int l = l0 + r;
        const size_t off = ((size_t)n * L + l) * S;
        const float ir = 1.0f / g_rowsum[n * L + l];
        float rmax = 0.0f; int rarg = t;
        #pragma unroll
        for (int k = 0; k < 25; k++) {
            int s = t + k * 256;
            float e = __half2float(Eh[off + s]);
            float c = e * e * ir * ic[k];
            conf[off + s] = c;
            cm[k] = fmaxf(cm[k], c);
            if (c > rmax) { rmax = c; rarg = s; }
        }
        #pragma unroll
        for (int o = 16; o; o >>= 1) {
            float ov = __shfl_xor_sync(0xFFFFFFFFu, rmax, o);
            int   oa = __shfl_xor_sync(0xFFFFFFFFu, rarg, o);
            if (ov > rmax) { rmax = ov; rarg = oa; }
        }
        if ((t & 31) == 0) { s_val[t >> 5] = rmax; s_arg[t >> 5] = rarg; }
        __syncthreads();
        if (t == 0) {
            #pragma unroll
            for (int w = 1; w < 8; w++)
                if (s_val[w] > rmax) { rmax = s_val[w]; rarg = s_arg[w]; }
            g_rowmax[n * L + l] = rmax;
            g_rowarg[n * L + l] = rarg;
        }
        __syncthreads();
    }
    #pragma unroll
    for (int k = 0; k < 25; k++)
        atomicMax(&g_colmax[n * S + t + k * 256], __float_as_int(cm[k]));
}

// ---------------------------------------------------------------------------
// 3) dense final: writes full mask + scores rows
// ---------------------------------------------------------------------------
__device__ __forceinline__ bool border_ok(int i) {
    int h = i / GRID_W, w = i % GRID_W;
    return (h >= BORDER) && (h < GRID_W - BORDER) && (w >= BORDER) && (w < GRID_W - BORDER);
}
__global__ __launch_bounds__(256) void final_dense_k(float* __restrict__ maskp,
                                                     float* __restrict__ scoresp) {
    const int n = blockIdx.y, l = blockIdx.x;
    const int t = threadIdx.x;
    const size_t off = ((size_t)n * L + l) * S;
    const float rmax = g_rowmax[n * L + l];
    const int rarg = g_rowarg[n * L + l];
    const bool rcond = (rmax > THRESH) && border_ok(l) &&
                       (__float_as_int(rmax) == g_colmax[n * S + rarg]) &&
                       border_ok(rarg);
    #pragma unroll
    for (int k = 0; k < 25; k++) {
        int s = t + k * 256;
        bool m = rcond && (s == rarg);
        maskp[off + s]   = m ? 1.0f : 0.0f;
        scoresp[off + s] = m ? rmax : 0.0f;
    }
}

// ---------------------------------------------------------------------------
extern "C" void kernel_launch(void* const* d_in, const int* in_sizes, int n_in,
                              void* d_out, int out_size) {
    const float* x0 = (const float*)d_in[0];
    const float* x1 = (const float*)d_in[1];

    float* conf    = (float*)d_out;          // [NB, L, S]
    float* maskp   = conf + NLS;             // [NB, L, S]
    float* scoresp = conf + 2 * NLS;         // [NB, L, S]
    __half* Eh     = (__half*)scoresp;       // fp16 E scratch in scores region
                                             // (consumed by conf_k before
                                             //  final_dense_k overwrites)

    cudaFuncSetAttribute(gemm_exp_k, cudaFuncAttributeMaxDynamicSharedMemorySize, SMEM_BYTES);

    cvt_k<<<(2 * CVT_CHUNKS + 255) / 256, 256>>>((const float4*)x0, (const float4*)x1);
    gemm_exp_k<<<dim3(S / BN, L / BM, NB), 128, SMEM_BYTES>>>(Eh);
    conf_k<<<dim3(L / CROWS, NB), 256>>>(Eh, conf);
    final_dense_k<<<dim3(L, NB), 256>>>(maskp, scoresp);
}

// round 17
// speedup vs baseline: 1.2513x; 1.1401x over previous
#include <cuda_runtime.h>
#include <cuda_fp16.h>
#include <mma.h>
#include <cstdint>
using namespace nvcuda;

#define NB 2
#define L 6400
#define S 6400
#define C 256
#define GRID_W 80
#define BORDER 2

static constexpr float SIM_SCALE = 1.0f / 25.6f;   // 1/(C*TEMPERATURE)
static constexpr float THRESH = 0.2f;
static constexpr long long NLS = (long long)NB * L * S;

#define BM 128
#define BN 128
#define BK 32
#define NKT (C / BK)            // 8
#define STAGES 3
#define SSTR 40                 // smem half stride (80B rows: conflict-free LDSM)
#define STAGE_STRIDE 132        // floats
#define TILE_BYTES ((BM + BN) * SSTR * 2)      // 20480 per stage
#define STAGE_BYTES (BM * STAGE_STRIDE * 4)    // 67584
#define SMEM_BYTES  (STAGE_BYTES)              // > 3*TILE_BYTES (61440)

// ---- small scratch only (large scratch must alias d_out: measured +225us
// penalty for big __device__ statics on this setup) ----
__device__ __align__(16) __half g_h0[NB * L * C];
__device__ __align__(16) __half g_h1[NB * S * C];
__device__ float g_rowsum[NB * L];
__device__ float g_colsum[NB * S];
__device__ float g_rowmax[NB * L];
__device__ int   g_rowarg[NB * L];
__device__ int   g_colmax[NB * S];   // float bits; conf > 0 so int order == float order

// ---------------------------------------------------------------------------
__device__ __forceinline__ uint32_t smem_u32(const void* p) {
    uint32_t a;
    asm("{ .reg .u64 t; cvta.to.shared.u64 t, %1; cvt.u32.u64 %0, t; }" : "=r"(a) : "l"(p));
    return a;
}
__device__ __forceinline__ void cp_async16(uint32_t saddr, const void* gaddr) {
    asm volatile("cp.async.cg.shared.global [%0], [%1], 16;" :: "r"(saddr), "l"(gaddr));
}
#define CP_COMMIT() asm volatile("cp.async.commit_group;" ::: "memory")
#define CP_WAIT(n)  asm volatile("cp.async.wait_group %0;" :: "n"(n) : "memory")

// ---------------------------------------------------------------------------
// 0) float -> half conversion + stats zeroing (fused; runs every replay)
// ---------------------------------------------------------------------------
#define CVT_CHUNKS (NB * L * C / 4)
__global__ __launch_bounds__(256) void cvt_k(const float4* __restrict__ x0,
                                             const float4* __restrict__ x1) {
    int i = blockIdx.x * blockDim.x + threadIdx.x;
    if (i < NB * S) { g_colsum[i] = 0.0f; g_colmax[i] = 0; g_rowsum[i] = 0.0f; }
    if (i < CVT_CHUNKS) {
        float4 v = x0[i];
        __half2* o = (__half2*)g_h0;
        o[2 * i]     = __floats2half2_rn(v.x, v.y);
        o[2 * i + 1] = __floats2half2_rn(v.z, v.w);
    } else if (i < 2 * CVT_CHUNKS) {
        int j = i - CVT_CHUNKS;
        float4 v = x1[j];
        __half2* o = (__half2*)g_h1;
        o[2 * j]     = __floats2half2_rn(v.x, v.y);
        o[2 * j + 1] = __floats2half2_rn(v.z, v.w);
    }
}

// ---------------------------------------------------------------------------
// 1) FP16 WMMA GEMM: 128x128 CTA tile, 4 warps x 64x64 warp tiles,
//    3-stage cp.async, 3 CTAs/SM, conflict-free 80B smem rows; epilogue:
//    exp -> smem stage -> row sums (LDS loop) + col sums folded in E-store
//    (frozen R16 config — GEMM at its legacy-HMMA plateau)
// ---------------------------------------------------------------------------
__global__ __launch_bounds__(128, 3) void gemm_exp_k(__half* __restrict__ Eh) {
    extern __shared__ char smem[];
    const uint32_t sb = smem_u32(smem);
    float* stage = (float*)smem;        // overlays stage buffers after mainloop

    const int t = threadIdx.x;
    const int wid = t >> 5;
    const int lid = t & 31;
    const int wm = wid >> 1;       // 0..1 -> 64-row band
    const int wn = wid & 1;        // 0..1 -> 64-col band
    const int n = blockIdx.z;
    const int l0 = blockIdx.y * BM, s0 = blockIdx.x * BN;

    const __half* A = g_h0 + (size_t)n * L * C;
    const __half* B = g_h1 + (size_t)n * S * C;
    __half* Eo = Eh + (size_t)n * L * S;

    wmma::fragment<wmma::accumulator, 16, 16, 16, float> acc[4][4];
    #pragma unroll
    for (int i = 0; i < 4; i++)
        #pragma unroll
        for (int j = 0; j < 4; j++)
            wmma::fill_fragment(acc[i][j], 0.0f);

    // tile loader: A 128x32 + B 128x32 = 1024 16B-chunks, 8 per thread
    auto load_tile = [&](int kt) {
        const int k0 = kt * BK;
        const uint32_t st = (kt % STAGES) * TILE_BYTES;
        #pragma unroll
        for (int i = 0; i < 4; i++) {
            int c = t + i * 128;               // 0..511
            int r = c >> 2, u = c & 3;
            uint32_t so = st + (uint32_t)(r * SSTR + u * 8) * 2;
            cp_async16(sb + so, A + (size_t)(l0 + r) * C + k0 + u * 8);
            cp_async16(sb + so + BM * SSTR * 2, B + (size_t)(s0 + r) * C + k0 + u * 8);
        }
        CP_COMMIT();
    };

    load_tile(0);
    load_tile(1);

    for (int kt = 0; kt < NKT; kt++) {
        CP_WAIT(1);
        __syncthreads();
        if (kt + 2 < NKT) load_tile(kt + 2);
        else              CP_COMMIT();

        const __half* Ab = (const __half*)(smem + (kt % STAGES) * TILE_BYTES);
        const __half* Bb = Ab + BM * SSTR;
        #pragma unroll
        for (int ks = 0; ks < BK; ks += 16) {
            wmma::fragment<wmma::matrix_a, 16, 16, 16, __half, wmma::row_major> af[4];
            wmma::fragment<wmma::matrix_b, 16, 16, 16, __half, wmma::col_major> bf[4];
            #pragma unroll
            for (int i = 0; i < 4; i++)
                wmma::load_matrix_sync(af[i], Ab + (wm * 64 + i * 16) * SSTR + ks, SSTR);
            #pragma unroll
            for (int j = 0; j < 4; j++)
                wmma::load_matrix_sync(bf[j], Bb + (wn * 64 + j * 16) * SSTR + ks, SSTR);
            #pragma unroll
            for (int i = 0; i < 4; i++)
                #pragma unroll
                for (int j = 0; j < 4; j++)
                    wmma::mma_sync(acc[i][j], af[i], bf[j], acc[i][j]);
        }
    }
    __syncthreads();

    // exp on accumulators, stage to smem (fp32)
    #pragma unroll
    for (int i = 0; i < 4; i++) {
        #pragma unroll
        for (int j = 0; j < 4; j++) {
            #pragma unroll
            for (int e = 0; e < acc[i][j].num_elements; e++)
                acc[i][j].x[e] = __expf(acc[i][j].x[e] * SIM_SCALE);
            wmma::store_matrix_sync(
                &stage[(size_t)(wm * 64 + i * 16) * STAGE_STRIDE + wn * 64 + j * 16],
                acc[i][j], STAGE_STRIDE, wmma::mem_row_major);
        }
    }
    __syncthreads();

    {   // row partial sums: thread t -> full row t (32 float4, vectorized)
        float s = 0.0f;
        const float4* row4 = (const float4*)&stage[t * STAGE_STRIDE];
        #pragma unroll 8
        for (int c = 0; c < 32; c++) {
            float4 f = row4[c];
            s += (f.x + f.y) + (f.z + f.w);
        }
        atomicAdd(&g_rowsum[n * L + l0 + t], s);
    }

    // E-store loop with col sums folded in: iteration it covers
    // r = wid + it*4 (whole warp on one row), q = lid (fixed cols per thread)
    float cs0 = 0.0f, cs1 = 0.0f, cs2 = 0.0f, cs3 = 0.0f;   // cols lid*4..lid*4+3
    #pragma unroll
    for (int it = 0; it < 32; it++) {
        const int r = wid + it * 4;
        float4 f = *(float4*)&stage[r * STAGE_STRIDE + lid * 4];
        cs0 += f.x; cs1 += f.y; cs2 += f.z; cs3 += f.w;
        __half2 h0 = __floats2half2_rn(f.x, f.y);
        __half2 h1 = __floats2half2_rn(f.z, f.w);
        uint2 u;
        u.x = *(uint32_t*)&h0;
        u.y = *(uint32_t*)&h1;
        *(uint2*)&Eo[(size_t)(l0 + r) * S + s0 + lid * 4] = u;
    }
    __syncthreads();   // all stage reads done; reuse it for the col exchange

    // col partials: group wid holds cols lid*4..lid*4+3; reduce the 4 groups
    float* sm_col = stage;                      // [4][128] floats
    sm_col[wid * 128 + lid * 4 + 0] = cs0;
    sm_col[wid * 128 + lid * 4 + 1] = cs1;
    sm_col[wid * 128 + lid * 4 + 2] = cs2;
    sm_col[wid * 128 + lid * 4 + 3] = cs3;
    __syncthreads();
    {
        float s = sm_col[t] + sm_col[128 + t] + sm_col[256 + t] + sm_col[384 + t];
        atomicAdd(&g_colsum[n * S + s0 + t], s);
    }
}

// ---------------------------------------------------------------------------
// 2) conf = E^2/(rowsum*colsum); rowmax+argmax, colmax — vectorized:
//    320 threads, thread t owns cols 4t+1280k (k<5): uint2 E loads,
//    float4 conf stores
// ---------------------------------------------------------------------------
#define CROWS 32
#define CTH 320
__global__ __launch_bounds__(CTH) void conf_k(const __half* __restrict__ Eh,
                                              float* __restrict__ conf) {
    const int n = blockIdx.y;
    const int l0 = blockIdx.x * CROWS;
    const int t = threadIdx.x;
    __shared__ float s_val[10];
    __shared__ int   s_arg[10];

    float ic[20], cm[20];
    #pragma unroll
    for (int k = 0; k < 5; k++) {
        const int c0 = 4 * t + 1280 * k;
        #pragma unroll
        for (int j = 0; j < 4; j++) {
            ic[k * 4 + j] = 1.0f / g_colsum[n * S + c0 + j];
            cm[k * 4 + j] = 0.0f;
        }
    }

    for (int r = 0; r < CROWS; r++) {
        const int l = l0 + r;
        const size_t off = ((size_t)n * L + l) * S;
        const float ir = 1.0f / g_rowsum[n * L + l];
        float rmax = 0.0f; int rarg = 4 * t;
        #pragma unroll
        for (int k = 0; k < 5; k++) {
            const int c0 = 4 * t + 1280 * k;
            uint2 u = *(const uint2*)&Eh[off + c0];
            __half2 h0 = *(__half2*)&u.x;
            __half2 h1 = *(__half2*)&u.y;
            float2 e01 = __half22float2(h0);
            float2 e23 = __half22float2(h1);
            float4 cf;
            cf.x = e01.x * e01.x * ir * ic[k * 4 + 0];
            cf.y = e01.y * e01.y * ir * ic[k * 4 + 1];
            cf.z = e23.x * e23.x * ir * ic[k * 4 + 2];
            cf.w = e23.y * e23.y * ir * ic[k * 4 + 3];
            *(float4*)&conf[off + c0] = cf;
            cm[k * 4 + 0] = fmaxf(cm[k * 4 + 0], cf.x);
            cm[k * 4 + 1] = fmaxf(cm[k * 4 + 1], cf.y);
            cm[k * 4 + 2] = fmaxf(cm[k * 4 + 2], cf.z);
            cm[k * 4 + 3] = fmaxf(cm[k * 4 + 3], cf.w);
            if (cf.x > rmax) { rmax = cf.x; rarg = c0 + 0; }
            if (cf.y > rmax) { rmax = cf.y; rarg = c0 + 1; }
            if (cf.z > rmax) { rmax = cf.z; rarg = c0 + 2; }
            if (cf.w > rmax) { rmax = cf.w; rarg = c0 + 3; }
        }
        #pragma unroll
        for (int o = 16; o; o >>= 1) {
            float ov = __shfl_xor_sync(0xFFFFFFFFu, rmax, o);
            int   oa = __shfl_xor_sync(0xFFFFFFFFu, rarg, o);
            if (ov > rmax) { rmax = ov; rarg = oa; }
        }
        if ((t & 31) == 0) { s_val[t >> 5] = rmax; s_arg[t >> 5] = rarg; }
        __syncthreads();
        if (t == 0) {
            #pragma unroll
            for (int w = 1; w < 10; w++)
                if (s_val[w] > rmax) { rmax = s_val[w]; rarg = s_arg[w]; }
            g_rowmax[n * L + l] = rmax;
            g_rowarg[n * L + l] = rarg;
        }
        __syncthreads();
    }
    #pragma unroll
    for (int k = 0; k < 5; k++) {
        const int c0 = 4 * t + 1280 * k;
        #pragma unroll
        for (int j = 0; j < 4; j++)
            atomicMax(&g_colmax[n * S + c0 + j], __float_as_int(cm[k * 4 + j]));
    }
}

// ---------------------------------------------------------------------------
// 3) dense final — vectorized float4 mask/scores stores (320 threads)
// ---------------------------------------------------------------------------
__device__ __forceinline__ bool border_ok(int i) {
    int h = i / GRID_W, w = i % GRID_W;
    return (h >= BORDER) && (h < GRID_W - BORDER) && (w >= BORDER) && (w < GRID_W - BORDER);
}
__global__ __launch_bounds__(CTH) void final_dense_k(float* __restrict__ maskp,
                                                     float* __restrict__ scoresp) {
    const int n = blockIdx.y, l = blockIdx.x;
    const int t = threadIdx.x;
    const size_t off = ((size_t)n * L + l) * S;
    const float rmax = g_rowmax[n * L + l];
    const int rarg = g_rowarg[n * L + l];
    const bool rcond = (rmax > THRESH) && border_ok(l) &&
                       (__float_as_int(rmax) == g_colmax[n * S + rarg]) &&
                       border_ok(rarg);
    #pragma unroll
    for (int k = 0; k < 5; k++) {
        const int c0 = 4 * t + 1280 * k;
        float4 mv = make_float4(0.0f, 0.0f, 0.0f, 0.0f);
        float4 sv = make_float4(0.0f, 0.0f, 0.0f, 0.0f);
        if (rcond && rarg >= c0 && rarg < c0 + 4) {
            int j = rarg - c0;
            (&mv.x)[j] = 1.0f;
            (&sv.x)[j] = rmax;
        }
        *(float4*)&maskp[off + c0]   = mv;
        *(float4*)&scoresp[off + c0] = sv;
    }
}

// ---------------------------------------------------------------------------
extern "C" void kernel_launch(void* const* d_in, const int* in_sizes, int n_in,
                              void* d_out, int out_size) {
    const float* x0 = (const float*)d_in[0];
    const float* x1 = (const float*)d_in[1];

    float* conf    = (float*)d_out;          // [NB, L, S]
    float* maskp   = conf + NLS;             // [NB, L, S]
    float* scoresp = conf + 2 * NLS;         // [NB, L, S]
    __half* Eh     = (__half*)scoresp;       // fp16 E scratch in scores region
                                             // (consumed by conf_k before
                                             //  final_dense_k overwrites)

    cudaFuncSetAttribute(gemm_exp_k, cudaFuncAttributeMaxDynamicSharedMemorySize, SMEM_BYTES);

    cvt_k<<<(2 * CVT_CHUNKS + 255) / 256, 256>>>((const float4*)x0, (const float4*)x1);
    gemm_exp_k<<<dim3(S / BN, L / BM, NB), 128, SMEM_BYTES>>>(Eh);
    conf_k<<<dim3(L / CROWS, NB), CTH>>>(Eh, conf);
    final_dense_k<<<dim3(L, NB), CTH>>>(maskp, scoresp);
}